// round 16
// baseline (speedup 1.0000x reference)
#include <cuda_runtime.h>
#include <stdint.h>
#include <math.h>

// Problem constants
constexpr int NB = 64;    // batch
constexpr int NT = 256;   // time
constexpr int ND = 256;   // embed dim
constexpr int NH = 256;   // hidden per direction
constexpr int NC = 32;    // tags
constexpr int NG = 1024;  // 4*NH gate rows

// Scratch (static device allocations; no cudaMalloc allowed)
__device__ __align__(16) float g_gates[(size_t)2 * NB * NT * NG];
__device__ __align__(16) float g_h[(size_t)2 * NB * NT * NH];
__device__ __align__(16) float g_em[(size_t)NB * NT * NC];
__device__ __align__(16) float g_wOutT[(size_t)2 * NH * NC];

// Fast activations (MUFU-based; ~1e-6 rel err, budget is 1e-3).
__device__ __forceinline__ float sigf(float x) {
    return __fdividef(1.0f, 1.0f + __expf(-x));
}
__device__ __forceinline__ float tanh_fast(float x) {
    float e = __expf(2.0f * x);
    return __fdividef(e - 1.0f, e + 1.0f);
}

// Packed fp32x2 helpers (Blackwell FFMA2; bit-exact fp32 FMA semantics per lane)
__device__ __forceinline__ void fma2(unsigned long long& d, unsigned long long a,
                                     unsigned long long b) {
    asm("fma.rn.f32x2 %0, %1, %2, %0;" : "+l"(d) : "l"(a), "l"(b));
}
__device__ __forceinline__ unsigned long long pk2(float x, float y) {
    unsigned long long r;
    asm("mov.b64 %0, {%1, %2};" : "=l"(r) : "r"(__float_as_uint(x)), "r"(__float_as_uint(y)));
    return r;
}
__device__ __forceinline__ float lo2(unsigned long long v) {
    return __uint_as_float((unsigned)(v & 0xffffffffull));
}
__device__ __forceinline__ float hi2(unsigned long long v) {
    return __uint_as_float((unsigned)(v >> 32));
}

// ---------------------------------------------------------------------------
// Dummy kernel: 1 dummy -> ncu fixed capture window lands on lstm_cluster.
// ---------------------------------------------------------------------------
__global__ void dummy_kernel() {}

// ---------------------------------------------------------------------------
// Kernel 0: transpose w_out [32][512] -> g_wOutT[512][32]
// ---------------------------------------------------------------------------
__global__ void transpose_wout_kernel(const float* __restrict__ w)
{
    __shared__ float tile[32][33];
    const int k0 = blockIdx.x * 32;
    const int tx = threadIdx.x, ty = threadIdx.y;
#pragma unroll
    for (int i = 0; i < 32; i += 8)
        tile[ty + i][tx] = w[(size_t)(ty + i) * (2 * NH) + k0 + tx];
    __syncthreads();
#pragma unroll
    for (int i = 0; i < 32; i += 8)
        g_wOutT[(size_t)(k0 + ty + i) * NC + tx] = tile[tx][ty + i];
}

// ---------------------------------------------------------------------------
// Kernel 1: embedding gather + input projection (both directions).
// SGEMM: BM=128, BN=128, BK=16, 256 threads, 8x8 microtile, f32x2 inner.
// ---------------------------------------------------------------------------
__global__ void __launch_bounds__(256) input_proj_kernel(
    const int* __restrict__ sent, const int* __restrict__ lens,
    const float* __restrict__ emb,
    const float* __restrict__ w_f, const float* __restrict__ bi_f, const float* __restrict__ bh_f,
    const float* __restrict__ w_b, const float* __restrict__ bi_b, const float* __restrict__ bh_b)
{
    const int dir = blockIdx.y >> 3;
    const int n0  = (blockIdx.y & 7) * 128;
    const int m0  = blockIdx.x * 128;

    const float* __restrict__ W  = dir ? w_b  : w_f;
    const float* __restrict__ BI = dir ? bi_b : bi_f;
    const float* __restrict__ BH = dir ? bh_b : bh_f;

    __shared__ __align__(16) float As[2][16][128];
    __shared__ __align__(16) float Bs[2][16][128];
    __shared__ int toks[128];

    const int tid = threadIdx.x;
    if (tid < 128) {
        int m = m0 + tid;
        int b = m >> 8, t = m & 255;
        int ts = t;
        if (dir) { int len = lens[b]; if (t < len) ts = len - 1 - t; }
        toks[tid] = sent[b * NT + ts];
    }
    __syncthreads();

    const int lrow2 = tid >> 2;
    const int lane4 = tid & 3;
    const int row0 = lrow2, row1 = lrow2 + 64;
    const float* arow0 = emb + (size_t)toks[row0] * ND + lane4 * 4;
    const float* arow1 = emb + (size_t)toks[row1] * ND + lane4 * 4;
    const float* brow0 = W + (size_t)(n0 + row0) * ND + lane4 * 4;
    const float* brow1 = W + (size_t)(n0 + row1) * ND + lane4 * 4;

    const int tx = tid & 15, ty = tid >> 4;

    unsigned long long acc2[8][4];
#pragma unroll
    for (int i = 0; i < 8; i++)
#pragma unroll
        for (int j = 0; j < 4; j++) acc2[i][j] = 0ull;

    {
        float4 a0 = *(const float4*)(arow0);
        float4 a1 = *(const float4*)(arow1);
        float4 b0 = *(const float4*)(brow0);
        float4 b1 = *(const float4*)(brow1);
        As[0][lane4 * 4 + 0][row0] = a0.x; As[0][lane4 * 4 + 1][row0] = a0.y;
        As[0][lane4 * 4 + 2][row0] = a0.z; As[0][lane4 * 4 + 3][row0] = a0.w;
        As[0][lane4 * 4 + 0][row1] = a1.x; As[0][lane4 * 4 + 1][row1] = a1.y;
        As[0][lane4 * 4 + 2][row1] = a1.z; As[0][lane4 * 4 + 3][row1] = a1.w;
        Bs[0][lane4 * 4 + 0][row0] = b0.x; Bs[0][lane4 * 4 + 1][row0] = b0.y;
        Bs[0][lane4 * 4 + 2][row0] = b0.z; Bs[0][lane4 * 4 + 3][row0] = b0.w;
        Bs[0][lane4 * 4 + 0][row1] = b1.x; Bs[0][lane4 * 4 + 1][row1] = b1.y;
        Bs[0][lane4 * 4 + 2][row1] = b1.z; Bs[0][lane4 * 4 + 3][row1] = b1.w;
    }
    __syncthreads();

    for (int it = 0; it < 16; ++it) {
        const int cb = it & 1, nb = cb ^ 1;
        float4 pa0, pa1, pb0, pb1;
        const bool pf = (it < 15);
        if (pf) {
            int kk = (it + 1) * 16;
            pa0 = *(const float4*)(arow0 + kk);
            pa1 = *(const float4*)(arow1 + kk);
            pb0 = *(const float4*)(brow0 + kk);
            pb1 = *(const float4*)(brow1 + kk);
        }
#pragma unroll
        for (int k = 0; k < 16; ++k) {
            float4 av0 = *(const float4*)&As[cb][k][ty * 8];
            float4 av1 = *(const float4*)&As[cb][k][ty * 8 + 4];
            ulonglong2 bw0 = *(const ulonglong2*)&Bs[cb][k][tx * 8];
            ulonglong2 bw1 = *(const ulonglong2*)&Bs[cb][k][tx * 8 + 4];
            unsigned long long b2[4] = {bw0.x, bw0.y, bw1.x, bw1.y};
            unsigned long long a2[8];
            a2[0] = pk2(av0.x, av0.x); a2[1] = pk2(av0.y, av0.y);
            a2[2] = pk2(av0.z, av0.z); a2[3] = pk2(av0.w, av0.w);
            a2[4] = pk2(av1.x, av1.x); a2[5] = pk2(av1.y, av1.y);
            a2[6] = pk2(av1.z, av1.z); a2[7] = pk2(av1.w, av1.w);
#pragma unroll
            for (int i = 0; i < 8; i++)
#pragma unroll
                for (int j = 0; j < 4; j++) fma2(acc2[i][j], a2[i], b2[j]);
        }
        if (pf) {
            As[nb][lane4 * 4 + 0][row0] = pa0.x; As[nb][lane4 * 4 + 1][row0] = pa0.y;
            As[nb][lane4 * 4 + 2][row0] = pa0.z; As[nb][lane4 * 4 + 3][row0] = pa0.w;
            As[nb][lane4 * 4 + 0][row1] = pa1.x; As[nb][lane4 * 4 + 1][row1] = pa1.y;
            As[nb][lane4 * 4 + 2][row1] = pa1.z; As[nb][lane4 * 4 + 3][row1] = pa1.w;
            Bs[nb][lane4 * 4 + 0][row0] = pb0.x; Bs[nb][lane4 * 4 + 1][row0] = pb0.y;
            Bs[nb][lane4 * 4 + 2][row0] = pb0.z; Bs[nb][lane4 * 4 + 3][row0] = pb0.w;
            Bs[nb][lane4 * 4 + 0][row1] = pb1.x; Bs[nb][lane4 * 4 + 1][row1] = pb1.y;
            Bs[nb][lane4 * 4 + 2][row1] = pb1.z; Bs[nb][lane4 * 4 + 3][row1] = pb1.w;
        }
        __syncthreads();
    }

    float bias[8];
#pragma unroll
    for (int j = 0; j < 8; j++) {
        int n = n0 + tx * 8 + j;
        bias[j] = BI[n] + BH[n];
    }
#pragma unroll
    for (int i = 0; i < 8; i++) {
        int m = m0 + ty * 8 + i;
        float* o = g_gates + ((size_t)dir * (NB * NT) + m) * NG + n0 + tx * 8;
        float4 s0, s1;
        s0.x = lo2(acc2[i][0]) + bias[0]; s0.y = hi2(acc2[i][0]) + bias[1];
        s0.z = lo2(acc2[i][1]) + bias[2]; s0.w = hi2(acc2[i][1]) + bias[3];
        s1.x = lo2(acc2[i][2]) + bias[4]; s1.y = hi2(acc2[i][2]) + bias[5];
        s1.z = lo2(acc2[i][3]) + bias[6]; s1.w = hi2(acc2[i][3]) + bias[7];
        *(float4*)o = s0;
        *(float4*)(o + 4) = s1;
    }
}

// ---------------------------------------------------------------------------
// Kernel 2: cluster LSTM — 512 THREADS (16 warps: 4/SMSP for latency hiding).
// Thread = (2 rows x 32-k-chunk): 32 u64 weight regs. Weights-in-regs,
// pipelined halves A/B, per-source mbarriers, fast activations (R15 protocol).
// hs: [2 ph][2 half][4 b][256]; gs: [2 half][8 kc][4 b][128].
// ---------------------------------------------------------------------------
constexpr int LS_H  = 4096;
constexpr int LS_G  = 8192;
constexpr int LS_MBAR_OFF = (LS_H + LS_G) * 4;   // 49152
constexpr int LSMEM_BYTES = LS_MBAR_OFF + 256;   // 32 mbarriers
constexpr unsigned TXB_S = 512u;                 // per-source per-half bytes

#define MBWAIT_CL(mbar, par) do {                                              \
    asm volatile(                                                              \
        "{\n\t.reg .pred P1;\n\t"                                              \
        "WL%=:\n\t"                                                            \
        "mbarrier.try_wait.parity.acquire.cluster.shared::cta.b64 P1, [%0], %1, 0x989680;\n\t" \
        "@P1 bra WD%=;\n\t"                                                    \
        "bra WL%=;\n\t"                                                        \
        "WD%=:\n\t}"                                                           \
        :: "r"(mbar), "r"(par) : "memory");                                    \
} while (0)

__global__ void __launch_bounds__(512, 1) __cluster_dims__(8, 1, 1)
lstm_cluster_kernel(const float* __restrict__ w_hh_f, const float* __restrict__ w_hh_b)
{
    extern __shared__ __align__(16) float smem[];
    float* hs = smem;                  // [2 ph][2 half][4 b][256]
    float* gs = smem + LS_H;           // [2 half][8 kc][4 b][128]

    const int tid = threadIdx.x;
    uint32_t rank;
    asm("mov.u32 %0, %%cluster_ctarank;" : "=r"(rank));
    const int cl = blockIdx.x >> 3;
    const int dir = cl & 1;
    const int bgrp = cl >> 1;

    const float* __restrict__ whh = dir ? w_hh_b : w_hh_f;

    const int sub = tid & 63;     // row-pair: rows 2*sub, 2*sub+1
    const int kc  = tid >> 6;     // k-chunk / source rank (2 warps per kc)

    // weights into registers: 2 rows x 16 packed f32x2 (k in [32kc,32kc+32))
    unsigned long long w2[32];
#pragma unroll
    for (int r = 0; r < 2; ++r) {
        int rr = 2 * sub + r;
        int gg = (rr >> 5) * 256 + 32 * (int)rank + (rr & 31);
        const float* wsrc = whh + (size_t)gg * NH + kc * 32;
#pragma unroll
        for (int p = 0; p < 16; ++p)
            w2[r * 16 + p] = *(const unsigned long long*)(wsrc + 2 * p);
    }

    uint32_t smem_base;
    asm("{ .reg .u64 t; cvta.to.shared.u64 t, %1; cvt.u32.u64 %0, t; }"
        : "=r"(smem_base) : "l"(smem));
    const uint32_t hs_sh = smem_base;
    const uint32_t mb_sh = smem_base + (uint32_t)LS_MBAR_OFF;
    // mb layout: A: mb_sh + (ph*8+src)*8 (128B); B: mb_sh + 128 + (ph*8+src)*8

    if (tid < 32) {
        uint32_t a = mb_sh + (uint32_t)(tid * 8);
        asm volatile("mbarrier.init.shared.b64 [%0], 1;" :: "r"(a) : "memory");
        asm volatile("mbarrier.arrive.expect_tx.shared.b64 _, [%0], %1;"
                     :: "r"(a), "r"(TXB_S) : "memory");
    }
    __syncthreads();

    asm volatile("barrier.cluster.arrive.aligned;" ::: "memory");
    asm volatile("barrier.cluster.wait.aligned;" ::: "memory");

    // remote hs bases; remote mbar = rhs[r] + LS_MBAR_OFF (mapa is linear per rank)
    uint32_t rhs[8];
#pragma unroll
    for (int r = 0; r < 8; ++r)
        asm("mapa.shared::cluster.u32 %0, %1, %2;" : "=r"(rhs[r]) : "r"(hs_sh), "r"(r));

    // activation mapping (tid<256): ab = tid>>5 (0..7); half = ab>>2; bb = ab&3
    const int ab = tid >> 5, aj = tid & 31;
    const int half = ab >> 2, bb = ab & 3;
    const bool is_act = (tid < 256);
    float c_reg = 0.0f;
    float* ghout = g_h + ((size_t)(dir * NB + bgrp * 8 + ab)) * (NT * NH) + 32 * (int)rank + aj;
    const float* gact = g_gates + ((size_t)(dir * NB + bgrp * 8 + ab)) * NT * NG
                        + 32 * (int)rank + aj;
    const uint32_t h_slot = (uint32_t)(((half * 4 + bb) * 256) + 32 * (int)rank + aj) * 4u;

    int pA = 0, pB = 0;   // parity per phase-slot pair; index by (cur)
    int pA0 = 0, pA1 = 0, pB0 = 0, pB1 = 0;

    // gi double buffer (act threads only)
    float gi0 = 0.f, gi1 = 0.f, gi2 = 0.f, gi3 = 0.f;
    if (is_act) { gi0 = gact[0]; gi1 = gact[256]; gi2 = gact[512]; gi3 = gact[768]; }
    (void)pA; (void)pB;

    for (int t = 0; t < NT; ++t) {
        const int cur = t & 1, nxt = cur ^ 1;

        // prefetch next step's gi
        float ni0 = 0.f, ni1 = 0.f, ni2 = 0.f, ni3 = 0.f;
        if (is_act && t + 1 < NT) {
            const float* gt = gact + (size_t)(t + 1) * NG;
            ni0 = gt[0]; ni1 = gt[256]; ni2 = gt[512]; ni3 = gt[768];
        }

        // ---- half A: per-source wait (both warps of kc wait; sub==0 re-arms)
        if (t > 0) {
            const uint32_t a_addr = mb_sh + (uint32_t)(cur * 64 + kc * 8);
            if (cur) { MBWAIT_CL(a_addr, pA1); pA1 ^= 1; }
            else     { MBWAIT_CL(a_addr, pA0); pA0 ^= 1; }
            if (sub == 0) {
                asm volatile("mbarrier.arrive.expect_tx.shared.b64 _, [%0], %1;"
                             :: "r"(a_addr), "r"(TXB_S) : "memory");
            }
        }

        // ---- kA: gate partials for batches 0..3 from hs[cur][A] (chunk kc)
        if (t > 0) {
#pragma unroll
            for (int b = 0; b < 4; ++b) {
                const ulonglong2* hb4 =
                    (const ulonglong2*)(hs + (cur * 2 + 0) * 1024 + b * 256 + kc * 32);
                unsigned long long a0 = 0ull, a1 = 0ull;
#pragma unroll
                for (int q = 0; q < 8; ++q) {
                    ulonglong2 hv = hb4[q];
                    fma2(a0, w2[2 * q], hv.x);      fma2(a0, w2[2 * q + 1], hv.y);
                    fma2(a1, w2[16 + 2 * q], hv.x); fma2(a1, w2[16 + 2 * q + 1], hv.y);
                }
                float2 part;
                part.x = lo2(a0) + hi2(a0);
                part.y = lo2(a1) + hi2(a1);
                *(float2*)&gs[((0 * 8 + kc) * 4 + b) * 128 + 2 * sub] = part;
            }
        }

        __syncthreads();   // sync1: gsA complete

        // ---- actA (tid 0-127) + send A's h — not gated on B's arrival
        if (is_act && half == 0) {
            float pi = gi0, pf = gi1, pg = gi2, po = gi3;
            if (t > 0) {
#pragma unroll
                for (int q = 0; q < 8; ++q) {
                    const float* gq = gs + ((0 * 8 + q) * 4 + bb) * 128 + aj;
                    pi += gq[0];
                    pf += gq[32];
                    pg += gq[64];
                    po += gq[96];
                }
            }
            float iv = sigf(pi), fv = sigf(pf), gv = tanh_fast(pg), ov = sigf(po);
            c_reg = fv * c_reg + iv * gv;
            float h = ov * tanh_fast(c_reg);
            ghout[(size_t)t * NH] = h;

            float hn = __shfl_down_sync(0xffffffffu, h, 1);
            if ((aj & 1) == 0) {
                unsigned long long hp =
                    ((unsigned long long)__float_as_uint(hn) << 32) |
                    (unsigned long long)__float_as_uint(h);
                const uint32_t dsto = (uint32_t)(nxt * 2048 * 4) + h_slot;
                const uint32_t mbo  = (uint32_t)(LS_MBAR_OFF + nxt * 64 + (int)rank * 8);
#pragma unroll
                for (int r = 0; r < 8; ++r) {
                    asm volatile(
                        "st.async.shared::cluster.mbarrier::complete_tx::bytes.b64 [%0], %1, [%2];"
                        :: "r"(rhs[r] + dsto), "l"(hp), "r"(rhs[r] + mbo) : "memory");
                }
            }
        }

        // ---- half B: per-source wait + re-arm (after sendA)
        if (t > 0) {
            const uint32_t b_addr = mb_sh + (uint32_t)(128 + cur * 64 + kc * 8);
            if (cur) { MBWAIT_CL(b_addr, pB1); pB1 ^= 1; }
            else     { MBWAIT_CL(b_addr, pB0); pB0 ^= 1; }
            if (sub == 0) {
                asm volatile("mbarrier.arrive.expect_tx.shared.b64 _, [%0], %1;"
                             :: "r"(b_addr), "r"(TXB_S) : "memory");
            }
        }

        // ---- kB: gate partials for batches 4..7 from hs[cur][B] (chunk kc)
        if (t > 0) {
#pragma unroll
            for (int b = 0; b < 4; ++b) {
                const ulonglong2* hb4 =
                    (const ulonglong2*)(hs + (cur * 2 + 1) * 1024 + b * 256 + kc * 32);
                unsigned long long a0 = 0ull, a1 = 0ull;
#pragma unroll
                for (int q = 0; q < 8; ++q) {
                    ulonglong2 hv = hb4[q];
                    fma2(a0, w2[2 * q], hv.x);      fma2(a0, w2[2 * q + 1], hv.y);
                    fma2(a1, w2[16 + 2 * q], hv.x); fma2(a1, w2[16 + 2 * q + 1], hv.y);
                }
                float2 part;
                part.x = lo2(a0) + hi2(a0);
                part.y = lo2(a1) + hi2(a1);
                *(float2*)&gs[((1 * 8 + kc) * 4 + b) * 128 + 2 * sub] = part;
            }
        }

        __syncthreads();   // sync2: gsB complete; orders gsA reads vs t+1 kA

        // ---- actB (tid 128-255) + send B's h
        if (is_act && half == 1) {
            float pi = gi0, pf = gi1, pg = gi2, po = gi3;
            if (t > 0) {
#pragma unroll
                for (int q = 0; q < 8; ++q) {
                    const float* gq = gs + ((1 * 8 + q) * 4 + bb) * 128 + aj;
                    pi += gq[0];
                    pf += gq[32];
                    pg += gq[64];
                    po += gq[96];
                }
            }
            float iv = sigf(pi), fv = sigf(pf), gv = tanh_fast(pg), ov = sigf(po);
            c_reg = fv * c_reg + iv * gv;
            float h = ov * tanh_fast(c_reg);
            ghout[(size_t)t * NH] = h;

            float hn = __shfl_down_sync(0xffffffffu, h, 1);
            if ((aj & 1) == 0) {
                unsigned long long hp =
                    ((unsigned long long)__float_as_uint(hn) << 32) |
                    (unsigned long long)__float_as_uint(h);
                const uint32_t dsto = (uint32_t)(nxt * 2048 * 4) + h_slot;
                const uint32_t mbo  = (uint32_t)(LS_MBAR_OFF + 128 + nxt * 64 + (int)rank * 8);
#pragma unroll
                for (int r = 0; r < 8; ++r) {
                    asm volatile(
                        "st.async.shared::cluster.mbarrier::complete_tx::bytes.b64 [%0], %1, [%2];"
                        :: "r"(rhs[r] + dsto), "l"(hp), "r"(rhs[r] + mbo) : "memory");
                }
            }
        }

        gi0 = ni0; gi1 = ni1; gi2 = ni2; gi3 = ni3;
    }

    // drain final sends (t=255: nxt=0 -> A[0][kc], B[0][kc])
    MBWAIT_CL(mb_sh + (uint32_t)(kc * 8), pA0);
    MBWAIT_CL(mb_sh + (uint32_t)(128 + kc * 8), pB0);
    asm volatile("barrier.cluster.arrive.aligned;" ::: "memory");
    asm volatile("barrier.cluster.wait.aligned;" ::: "memory");
}

// ---------------------------------------------------------------------------
// Kernel 3: emissions. One warp per (b,t); lane = tag. 4 acc chains.
// ---------------------------------------------------------------------------
__global__ void __launch_bounds__(256) emissions_kernel(
    const int* __restrict__ lens, const float* __restrict__ b_out)
{
    const int item = blockIdx.x * 8 + (threadIdx.x >> 5);
    const int lane = threadIdx.x & 31;
    const int b = item >> 8, t = item & 255;
    const int len = lens[b];
    const int tb = (t < len) ? (len - 1 - t) : t;

    const float* hf = g_h + ((size_t)0 * NB + b) * NT * NH + (size_t)t * NH;
    const float* hb = g_h + ((size_t)1 * NB + b) * NT * NH + (size_t)tb * NH;
    const float* __restrict__ wT = g_wOutT;

    float acc0 = b_out[lane], acc1 = 0.f, acc2 = 0.f, acc3 = 0.f;
#pragma unroll 4
    for (int k16 = 0; k16 < 16; ++k16) {
        float4 ha = *(const float4*)(hf + k16 * 16);
        float4 hbv = *(const float4*)(hf + k16 * 16 + 4);
        float4 hc = *(const float4*)(hf + k16 * 16 + 8);
        float4 hd = *(const float4*)(hf + k16 * 16 + 12);
        const float* w0 = wT + (k16 * 16) * NC + lane;
        acc0 = fmaf(ha.x, w0[0 * NC], acc0);  acc1 = fmaf(ha.y, w0[1 * NC], acc1);
        acc2 = fmaf(ha.z, w0[2 * NC], acc2);  acc3 = fmaf(ha.w, w0[3 * NC], acc3);
        acc0 = fmaf(hbv.x, w0[4 * NC], acc0); acc1 = fmaf(hbv.y, w0[5 * NC], acc1);
        acc2 = fmaf(hbv.z, w0[6 * NC], acc2); acc3 = fmaf(hbv.w, w0[7 * NC], acc3);
        acc0 = fmaf(hc.x, w0[8 * NC], acc0);  acc1 = fmaf(hc.y, w0[9 * NC], acc1);
        acc2 = fmaf(hc.z, w0[10 * NC], acc2); acc3 = fmaf(hc.w, w0[11 * NC], acc3);
        acc0 = fmaf(hd.x, w0[12 * NC], acc0); acc1 = fmaf(hd.y, w0[13 * NC], acc1);
        acc2 = fmaf(hd.z, w0[14 * NC], acc2); acc3 = fmaf(hd.w, w0[15 * NC], acc3);
    }
#pragma unroll 4
    for (int k16 = 0; k16 < 16; ++k16) {
        float4 ha = *(const float4*)(hb + k16 * 16);
        float4 hbv = *(const float4*)(hb + k16 * 16 + 4);
        float4 hc = *(const float4*)(hb + k16 * 16 + 8);
        float4 hd = *(const float4*)(hb + k16 * 16 + 12);
        const float* w0 = wT + (NH + k16 * 16) * NC + lane;
        acc0 = fmaf(ha.x, w0[0 * NC], acc0);  acc1 = fmaf(ha.y, w0[1 * NC], acc1);
        acc2 = fmaf(ha.z, w0[2 * NC], acc2);  acc3 = fmaf(ha.w, w0[3 * NC], acc3);
        acc0 = fmaf(hbv.x, w0[4 * NC], acc0); acc1 = fmaf(hbv.y, w0[5 * NC], acc1);
        acc2 = fmaf(hbv.z, w0[6 * NC], acc2); acc3 = fmaf(hbv.w, w0[7 * NC], acc3);
        acc0 = fmaf(hc.x, w0[8 * NC], acc0);  acc1 = fmaf(hc.y, w0[9 * NC], acc1);
        acc2 = fmaf(hc.z, w0[10 * NC], acc2); acc3 = fmaf(hc.w, w0[11 * NC], acc3);
        acc0 = fmaf(hd.x, w0[12 * NC], acc0); acc1 = fmaf(hd.y, w0[13 * NC], acc1);
        acc2 = fmaf(hd.z, w0[14 * NC], acc2); acc3 = fmaf(hd.w, w0[15 * NC], acc3);
    }
    g_em[(size_t)item * NC + lane] = (acc0 + acc1) + (acc2 + acc3);
}

// ---------------------------------------------------------------------------
// Kernel 4: Viterbi decode. One warp per batch element; lane = tag.
// ---------------------------------------------------------------------------
__global__ void __launch_bounds__(32) viterbi_kernel(
    const int* __restrict__ lens,
    const float* __restrict__ start_trans, const float* __restrict__ end_trans,
    const float* __restrict__ trans, float* __restrict__ out)
{
    const int b = blockIdx.x;
    const int lane = threadIdx.x;

    __shared__ int hist[NT - 1][NC];

    float tr[NC];
#pragma unroll
    for (int cp = 0; cp < NC; ++cp) tr[cp] = trans[cp * NC + lane];

    const int len = lens[b];
    const float* emp = g_em + (size_t)b * NT * NC;
    float score = start_trans[lane] + emp[lane];
    float em_next = emp[NC + lane];

    for (int t = 1; t < NT; ++t) {
        float best = -1e30f;
        int bp = 0;
#pragma unroll
        for (int cp = 0; cp < NC; ++cp) {
            float sc = __shfl_sync(0xffffffffu, score, cp) + tr[cp];
            if (sc > best) { best = sc; bp = cp; }
        }
        hist[t - 1][lane] = bp;
        float em_cur = em_next;
        if (t + 1 < NT) em_next = emp[(t + 1) * NC + lane];
        if (t < len) score = best + em_cur;
    }
    score += end_trans[lane];

    float v = score;
    int idx = lane;
#pragma unroll
    for (int off = 16; off; off >>= 1) {
        float v2 = __shfl_xor_sync(0xffffffffu, v, off);
        int i2 = __shfl_xor_sync(0xffffffffu, idx, off);
        if (v2 > v || (v2 == v && i2 < idx)) { v = v2; idx = i2; }
    }

    if (lane == 0) {
        out[NB * NT + b] = v;
        int tag = idx;
        out[(size_t)b * NT + (NT - 1)] = (float)tag;
        for (int t = NT - 2; t >= 0; --t) {
            if (t < len - 1) tag = hist[t][tag];
            out[(size_t)b * NT + t] = (float)tag;
        }
    }
}

// ---------------------------------------------------------------------------
extern "C" void kernel_launch(void* const* d_in, const int* in_sizes, int n_in,
                              void* d_out, int out_size)
{
    const int*   sent   = (const int*)d_in[0];
    const int*   lens   = (const int*)d_in[1];
    const float* emb    = (const float*)d_in[2];
    const float* w_ih_f = (const float*)d_in[3];
    const float* w_hh_f = (const float*)d_in[4];
    const float* b_ih_f = (const float*)d_in[5];
    const float* b_hh_f = (const float*)d_in[6];
    const float* w_ih_b = (const float*)d_in[7];
    const float* w_hh_b = (const float*)d_in[8];
    const float* b_ih_b = (const float*)d_in[9];
    const float* b_hh_b = (const float*)d_in[10];
    const float* w_out  = (const float*)d_in[11];
    const float* b_out  = (const float*)d_in[12];
    const float* start_trans = (const float*)d_in[13];
    const float* end_trans   = (const float*)d_in[14];
    const float* trans       = (const float*)d_in[15];
    float* out = (float*)d_out;

    cudaFuncSetAttribute(lstm_cluster_kernel,
                         cudaFuncAttributeMaxDynamicSharedMemorySize, LSMEM_BYTES);

    // 1 dummy: shifts ncu's fixed capture index onto lstm_cluster_kernel.
    dummy_kernel<<<1, 32>>>();

    dim3 tb(32, 8);
    transpose_wout_kernel<<<dim3((2 * NH) / 32, 1, 1), tb>>>(w_out);

    dim3 g1(128, 16);
    input_proj_kernel<<<g1, 256>>>(sent, lens, emb,
                                   w_ih_f, b_ih_f, b_hh_f,
                                   w_ih_b, b_ih_b, b_hh_b);
    lstm_cluster_kernel<<<128, 512, LSMEM_BYTES>>>(w_hh_f, w_hh_b);
    emissions_kernel<<<NB * NT / 8, 256>>>(lens, b_out);
    viterbi_kernel<<<NB, 32>>>(lens, start_trans, end_trans, trans, out);
}

// round 17
// speedup vs baseline: 1.0509x; 1.0509x over previous
#include <cuda_runtime.h>
#include <stdint.h>
#include <math.h>

// Problem constants
constexpr int NB = 64;    // batch
constexpr int NT = 256;   // time
constexpr int ND = 256;   // embed dim
constexpr int NH = 256;   // hidden per direction
constexpr int NC = 32;    // tags
constexpr int NG = 1024;  // 4*NH gate rows

// Scratch (static device allocations; no cudaMalloc allowed)
__device__ __align__(16) float g_gates[(size_t)2 * NB * NT * NG];
__device__ __align__(16) float g_h[(size_t)2 * NB * NT * NH];
__device__ __align__(16) float g_em[(size_t)NB * NT * NC];
__device__ __align__(16) float g_wOutT[(size_t)2 * NH * NC];

// Fast activations (MUFU-based; ~1e-6 rel err, budget is 1e-3).
__device__ __forceinline__ float sigf(float x) {
    return __fdividef(1.0f, 1.0f + __expf(-x));
}
__device__ __forceinline__ float tanh_fast(float x) {
    float e = __expf(2.0f * x);
    return __fdividef(e - 1.0f, e + 1.0f);
}

// Packed fp32x2 helpers (Blackwell FFMA2; bit-exact fp32 FMA semantics per lane)
__device__ __forceinline__ void fma2(unsigned long long& d, unsigned long long a,
                                     unsigned long long b) {
    asm("fma.rn.f32x2 %0, %1, %2, %0;" : "+l"(d) : "l"(a), "l"(b));
}
__device__ __forceinline__ unsigned long long pk2(float x, float y) {
    unsigned long long r;
    asm("mov.b64 %0, {%1, %2};" : "=l"(r) : "r"(__float_as_uint(x)), "r"(__float_as_uint(y)));
    return r;
}
__device__ __forceinline__ float lo2(unsigned long long v) {
    return __uint_as_float((unsigned)(v & 0xffffffffull));
}
__device__ __forceinline__ float hi2(unsigned long long v) {
    return __uint_as_float((unsigned)(v >> 32));
}

// ---------------------------------------------------------------------------
// Dummy kernel: 1 dummy -> ncu fixed capture window lands on lstm_cluster.
// ---------------------------------------------------------------------------
__global__ void dummy_kernel() {}

// ---------------------------------------------------------------------------
// Kernel 0: transpose w_out [32][512] -> g_wOutT[512][32]
// ---------------------------------------------------------------------------
__global__ void transpose_wout_kernel(const float* __restrict__ w)
{
    __shared__ float tile[32][33];
    const int k0 = blockIdx.x * 32;
    const int tx = threadIdx.x, ty = threadIdx.y;
#pragma unroll
    for (int i = 0; i < 32; i += 8)
        tile[ty + i][tx] = w[(size_t)(ty + i) * (2 * NH) + k0 + tx];
    __syncthreads();
#pragma unroll
    for (int i = 0; i < 32; i += 8)
        g_wOutT[(size_t)(k0 + ty + i) * NC + tx] = tile[tx][ty + i];
}

// ---------------------------------------------------------------------------
// Kernel 1: embedding gather + input projection (both directions).
// SGEMM: BM=128, BN=128, BK=16, 256 threads, 8x8 microtile, f32x2 inner.
// ---------------------------------------------------------------------------
__global__ void __launch_bounds__(256) input_proj_kernel(
    const int* __restrict__ sent, const int* __restrict__ lens,
    const float* __restrict__ emb,
    const float* __restrict__ w_f, const float* __restrict__ bi_f, const float* __restrict__ bh_f,
    const float* __restrict__ w_b, const float* __restrict__ bi_b, const float* __restrict__ bh_b)
{
    const int dir = blockIdx.y >> 3;
    const int n0  = (blockIdx.y & 7) * 128;
    const int m0  = blockIdx.x * 128;

    const float* __restrict__ W  = dir ? w_b  : w_f;
    const float* __restrict__ BI = dir ? bi_b : bi_f;
    const float* __restrict__ BH = dir ? bh_b : bh_f;

    __shared__ __align__(16) float As[2][16][128];
    __shared__ __align__(16) float Bs[2][16][128];
    __shared__ int toks[128];

    const int tid = threadIdx.x;
    if (tid < 128) {
        int m = m0 + tid;
        int b = m >> 8, t = m & 255;
        int ts = t;
        if (dir) { int len = lens[b]; if (t < len) ts = len - 1 - t; }
        toks[tid] = sent[b * NT + ts];
    }
    __syncthreads();

    const int lrow2 = tid >> 2;
    const int lane4 = tid & 3;
    const int row0 = lrow2, row1 = lrow2 + 64;
    const float* arow0 = emb + (size_t)toks[row0] * ND + lane4 * 4;
    const float* arow1 = emb + (size_t)toks[row1] * ND + lane4 * 4;
    const float* brow0 = W + (size_t)(n0 + row0) * ND + lane4 * 4;
    const float* brow1 = W + (size_t)(n0 + row1) * ND + lane4 * 4;

    const int tx = tid & 15, ty = tid >> 4;

    unsigned long long acc2[8][4];
#pragma unroll
    for (int i = 0; i < 8; i++)
#pragma unroll
        for (int j = 0; j < 4; j++) acc2[i][j] = 0ull;

    {
        float4 a0 = *(const float4*)(arow0);
        float4 a1 = *(const float4*)(arow1);
        float4 b0 = *(const float4*)(brow0);
        float4 b1 = *(const float4*)(brow1);
        As[0][lane4 * 4 + 0][row0] = a0.x; As[0][lane4 * 4 + 1][row0] = a0.y;
        As[0][lane4 * 4 + 2][row0] = a0.z; As[0][lane4 * 4 + 3][row0] = a0.w;
        As[0][lane4 * 4 + 0][row1] = a1.x; As[0][lane4 * 4 + 1][row1] = a1.y;
        As[0][lane4 * 4 + 2][row1] = a1.z; As[0][lane4 * 4 + 3][row1] = a1.w;
        Bs[0][lane4 * 4 + 0][row0] = b0.x; Bs[0][lane4 * 4 + 1][row0] = b0.y;
        Bs[0][lane4 * 4 + 2][row0] = b0.z; Bs[0][lane4 * 4 + 3][row0] = b0.w;
        Bs[0][lane4 * 4 + 0][row1] = b1.x; Bs[0][lane4 * 4 + 1][row1] = b1.y;
        Bs[0][lane4 * 4 + 2][row1] = b1.z; Bs[0][lane4 * 4 + 3][row1] = b1.w;
    }
    __syncthreads();

    for (int it = 0; it < 16; ++it) {
        const int cb = it & 1, nb = cb ^ 1;
        float4 pa0, pa1, pb0, pb1;
        const bool pf = (it < 15);
        if (pf) {
            int kk = (it + 1) * 16;
            pa0 = *(const float4*)(arow0 + kk);
            pa1 = *(const float4*)(arow1 + kk);
            pb0 = *(const float4*)(brow0 + kk);
            pb1 = *(const float4*)(brow1 + kk);
        }
#pragma unroll
        for (int k = 0; k < 16; ++k) {
            float4 av0 = *(const float4*)&As[cb][k][ty * 8];
            float4 av1 = *(const float4*)&As[cb][k][ty * 8 + 4];
            ulonglong2 bw0 = *(const ulonglong2*)&Bs[cb][k][tx * 8];
            ulonglong2 bw1 = *(const ulonglong2*)&Bs[cb][k][tx * 8 + 4];
            unsigned long long b2[4] = {bw0.x, bw0.y, bw1.x, bw1.y};
            unsigned long long a2[8];
            a2[0] = pk2(av0.x, av0.x); a2[1] = pk2(av0.y, av0.y);
            a2[2] = pk2(av0.z, av0.z); a2[3] = pk2(av0.w, av0.w);
            a2[4] = pk2(av1.x, av1.x); a2[5] = pk2(av1.y, av1.y);
            a2[6] = pk2(av1.z, av1.z); a2[7] = pk2(av1.w, av1.w);
#pragma unroll
            for (int i = 0; i < 8; i++)
#pragma unroll
                for (int j = 0; j < 4; j++) fma2(acc2[i][j], a2[i], b2[j]);
        }
        if (pf) {
            As[nb][lane4 * 4 + 0][row0] = pa0.x; As[nb][lane4 * 4 + 1][row0] = pa0.y;
            As[nb][lane4 * 4 + 2][row0] = pa0.z; As[nb][lane4 * 4 + 3][row0] = pa0.w;
            As[nb][lane4 * 4 + 0][row1] = pa1.x; As[nb][lane4 * 4 + 1][row1] = pa1.y;
            As[nb][lane4 * 4 + 2][row1] = pa1.z; As[nb][lane4 * 4 + 3][row1] = pa1.w;
            Bs[nb][lane4 * 4 + 0][row0] = pb0.x; Bs[nb][lane4 * 4 + 1][row0] = pb0.y;
            Bs[nb][lane4 * 4 + 2][row0] = pb0.z; Bs[nb][lane4 * 4 + 3][row0] = pb0.w;
            Bs[nb][lane4 * 4 + 0][row1] = pb1.x; Bs[nb][lane4 * 4 + 1][row1] = pb1.y;
            Bs[nb][lane4 * 4 + 2][row1] = pb1.z; Bs[nb][lane4 * 4 + 3][row1] = pb1.w;
        }
        __syncthreads();
    }

    float bias[8];
#pragma unroll
    for (int j = 0; j < 8; j++) {
        int n = n0 + tx * 8 + j;
        bias[j] = BI[n] + BH[n];
    }
#pragma unroll
    for (int i = 0; i < 8; i++) {
        int m = m0 + ty * 8 + i;
        float* o = g_gates + ((size_t)dir * (NB * NT) + m) * NG + n0 + tx * 8;
        float4 s0, s1;
        s0.x = lo2(acc2[i][0]) + bias[0]; s0.y = hi2(acc2[i][0]) + bias[1];
        s0.z = lo2(acc2[i][1]) + bias[2]; s0.w = hi2(acc2[i][1]) + bias[3];
        s1.x = lo2(acc2[i][2]) + bias[4]; s1.y = hi2(acc2[i][2]) + bias[5];
        s1.z = lo2(acc2[i][3]) + bias[6]; s1.w = hi2(acc2[i][3]) + bias[7];
        *(float4*)o = s0;
        *(float4*)(o + 4) = s1;
    }
}

// ---------------------------------------------------------------------------
// Kernel 2: cluster LSTM — R15 winner config (256 threads) with CTA-SCOPE
// mbarrier waits (st.async complete_tx delivery needs only .acquire.cta, the
// canonical Blackwell pattern; .acquire.cluster costs ~UCGABAR_WAIT ~490cyc).
// Weights in registers, pipelined halves A/B, per-source mbarriers, fast act.
// hs: [2 ph][2 half][4 b][256]; gs: [2 half][8 kc][4 b][128].
// ---------------------------------------------------------------------------
constexpr int LS_H  = 4096;
constexpr int LS_G  = 8192;
constexpr int LS_MBAR_OFF = (LS_H + LS_G) * 4;   // 49152
constexpr int LSMEM_BYTES = LS_MBAR_OFF + 256;   // 32 mbarriers
constexpr unsigned TXB_S = 512u;                 // per-source per-half bytes

#define MBWAIT_CTA(mbar, par) do {                                             \
    asm volatile(                                                              \
        "{\n\t.reg .pred P1;\n\t"                                              \
        "WL%=:\n\t"                                                            \
        "mbarrier.try_wait.parity.acquire.cta.shared::cta.b64 P1, [%0], %1, 0x989680;\n\t" \
        "@P1 bra WD%=;\n\t"                                                    \
        "bra WL%=;\n\t"                                                        \
        "WD%=:\n\t}"                                                           \
        :: "r"(mbar), "r"(par) : "memory");                                    \
} while (0)

__global__ void __launch_bounds__(256, 1) __cluster_dims__(8, 1, 1)
lstm_cluster_kernel(const float* __restrict__ w_hh_f, const float* __restrict__ w_hh_b)
{
    extern __shared__ __align__(16) float smem[];
    float* hs = smem;                  // [2 ph][2 half][4 b][256]
    float* gs = smem + LS_H;           // [2 half][8 kc][4 b][128]

    const int tid = threadIdx.x;
    uint32_t rank;
    asm("mov.u32 %0, %%cluster_ctarank;" : "=r"(rank));
    const int cl = blockIdx.x >> 3;
    const int dir = cl & 1;
    const int bgrp = cl >> 1;

    const float* __restrict__ whh = dir ? w_hh_b : w_hh_f;

    const int rg = tid & 31;      // row-group: rows 4rg..4rg+3
    const int kc = tid >> 5;      // k-chunk / source rank this warp consumes

    // weights into registers: 4 rows x 16 packed f32x2
    unsigned long long w2[64];
#pragma unroll
    for (int r = 0; r < 4; ++r) {
        int rr = 4 * rg + r;
        int gg = (rr >> 5) * 256 + 32 * (int)rank + (rr & 31);
        const float* wsrc = whh + (size_t)gg * NH + kc * 32;
#pragma unroll
        for (int p = 0; p < 16; ++p)
            w2[r * 16 + p] = *(const unsigned long long*)(wsrc + 2 * p);
    }

    uint32_t smem_base;
    asm("{ .reg .u64 t; cvta.to.shared.u64 t, %1; cvt.u32.u64 %0, t; }"
        : "=r"(smem_base) : "l"(smem));
    const uint32_t hs_sh = smem_base;
    const uint32_t mb_sh = smem_base + (uint32_t)LS_MBAR_OFF;
    // mb layout: A: mb_sh + (ph*8+src)*8 (128B); B: mb_sh + 128 + (ph*8+src)*8

    if (tid < 32) {
        uint32_t a = mb_sh + (uint32_t)(tid * 8);
        asm volatile("mbarrier.init.shared.b64 [%0], 1;" :: "r"(a) : "memory");
        asm volatile("mbarrier.arrive.expect_tx.shared.b64 _, [%0], %1;"
                     :: "r"(a), "r"(TXB_S) : "memory");
    }
    __syncthreads();

    asm volatile("barrier.cluster.arrive.aligned;" ::: "memory");
    asm volatile("barrier.cluster.wait.aligned;" ::: "memory");

    uint32_t rhs[8], rmb[8];
#pragma unroll
    for (int r = 0; r < 8; ++r) {
        asm("mapa.shared::cluster.u32 %0, %1, %2;" : "=r"(rhs[r]) : "r"(hs_sh), "r"(r));
        asm("mapa.shared::cluster.u32 %0, %1, %2;" : "=r"(rmb[r]) : "r"(mb_sh), "r"(r));
    }

    // activation mapping: ab = tid>>5 (0..7); half = ab>>2; bb = ab&3
    const int ab = tid >> 5, aj = tid & 31;
    const int half = ab >> 2, bb = ab & 3;
    float c_reg = 0.0f;
    float* ghout = g_h + ((size_t)(dir * NB + bgrp * 8 + ab)) * (NT * NH) + 32 * (int)rank + aj;
    const float* gact = g_gates + ((size_t)(dir * NB + bgrp * 8 + ab)) * NT * NG
                        + 32 * (int)rank + aj;
    const uint32_t h_slot = (uint32_t)(((half * 4 + bb) * 256) + 32 * (int)rank + aj) * 4u;

    int pA0 = 0, pA1 = 0, pB0 = 0, pB1 = 0;

    // gi double buffer: load t=0 now; prefetch t+1 inside the loop.
    float gi0 = gact[0], gi1 = gact[256], gi2 = gact[512], gi3 = gact[768];

    for (int t = 0; t < NT; ++t) {
        const int cur = t & 1, nxt = cur ^ 1;

        // prefetch next step's gi (covered by waits + compute of this step)
        float ni0 = 0.f, ni1 = 0.f, ni2 = 0.f, ni3 = 0.f;
        if (t + 1 < NT) {
            const float* gt = gact + (size_t)(t + 1) * NG;
            ni0 = gt[0]; ni1 = gt[256]; ni2 = gt[512]; ni3 = gt[768];
        }

        // ---- half A: per-source wait (warp kc waits only source kc) + re-arm
        if (t > 0) {
            const uint32_t a_addr = mb_sh + (uint32_t)(cur * 64 + kc * 8);
            if (cur) { MBWAIT_CTA(a_addr, pA1); pA1 ^= 1; }
            else     { MBWAIT_CTA(a_addr, pA0); pA0 ^= 1; }
            if (aj == 0) {
                asm volatile("mbarrier.arrive.expect_tx.shared.b64 _, [%0], %1;"
                             :: "r"(a_addr), "r"(TXB_S) : "memory");
            }
            __syncwarp();
        }

        // ---- kA: gate partials for batches 0..3 from hs[cur][A] (chunk kc)
        if (t > 0) {
#pragma unroll
            for (int b = 0; b < 4; ++b) {
                const ulonglong2* hb4 =
                    (const ulonglong2*)(hs + (cur * 2 + 0) * 1024 + b * 256 + kc * 32);
                unsigned long long a0 = 0ull, a1 = 0ull, a2 = 0ull, a3 = 0ull;
#pragma unroll
                for (int q = 0; q < 8; ++q) {
                    ulonglong2 hv = hb4[q];
                    fma2(a0, w2[0 * 16 + 2 * q], hv.x); fma2(a0, w2[0 * 16 + 2 * q + 1], hv.y);
                    fma2(a1, w2[1 * 16 + 2 * q], hv.x); fma2(a1, w2[1 * 16 + 2 * q + 1], hv.y);
                    fma2(a2, w2[2 * 16 + 2 * q], hv.x); fma2(a2, w2[2 * 16 + 2 * q + 1], hv.y);
                    fma2(a3, w2[3 * 16 + 2 * q], hv.x); fma2(a3, w2[3 * 16 + 2 * q + 1], hv.y);
                }
                float4 part;
                part.x = lo2(a0) + hi2(a0);
                part.y = lo2(a1) + hi2(a1);
                part.z = lo2(a2) + hi2(a2);
                part.w = lo2(a3) + hi2(a3);
                *(float4*)&gs[((0 * 8 + kc) * 4 + b) * 128 + 4 * rg] = part;
            }
        }

        __syncthreads();   // sync1: gsA complete

        // ---- actA (warps 0-3) + send A's h — NOT gated on B's arrival
        if (half == 0) {
            float pi = gi0, pf = gi1, pg = gi2, po = gi3;
            if (t > 0) {
#pragma unroll
                for (int q = 0; q < 8; ++q) {
                    const float* gq = gs + ((0 * 8 + q) * 4 + bb) * 128 + aj;
                    pi += gq[0];
                    pf += gq[32];
                    pg += gq[64];
                    po += gq[96];
                }
            }
            float iv = sigf(pi), fv = sigf(pf), gv = tanh_fast(pg), ov = sigf(po);
            c_reg = fv * c_reg + iv * gv;
            float h = ov * tanh_fast(c_reg);
            ghout[(size_t)t * NH] = h;

            float hn = __shfl_down_sync(0xffffffffu, h, 1);
            if ((aj & 1) == 0) {
                unsigned long long hp =
                    ((unsigned long long)__float_as_uint(hn) << 32) |
                    (unsigned long long)__float_as_uint(h);
                const uint32_t dsto = (uint32_t)(nxt * 2048 * 4) + h_slot;
                const uint32_t mbo  = (uint32_t)(nxt * 64 + (int)rank * 8);  // A[nxt][me]
#pragma unroll
                for (int r = 0; r < 8; ++r) {
                    asm volatile(
                        "st.async.shared::cluster.mbarrier::complete_tx::bytes.b64 [%0], %1, [%2];"
                        :: "r"(rhs[r] + dsto), "l"(hp), "r"(rmb[r] + mbo) : "memory");
                }
            }
        }

        // ---- half B: per-source wait + re-arm (after sendA)
        if (t > 0) {
            const uint32_t b_addr = mb_sh + (uint32_t)(128 + cur * 64 + kc * 8);
            if (cur) { MBWAIT_CTA(b_addr, pB1); pB1 ^= 1; }
            else     { MBWAIT_CTA(b_addr, pB0); pB0 ^= 1; }
            if (aj == 0) {
                asm volatile("mbarrier.arrive.expect_tx.shared.b64 _, [%0], %1;"
                             :: "r"(b_addr), "r"(TXB_S) : "memory");
            }
            __syncwarp();
        }

        // ---- kB: gate partials for batches 4..7 from hs[cur][B] (chunk kc)
        if (t > 0) {
#pragma unroll
            for (int b = 0; b < 4; ++b) {
                const ulonglong2* hb4 =
                    (const ulonglong2*)(hs + (cur * 2 + 1) * 1024 + b * 256 + kc * 32);
                unsigned long long a0 = 0ull, a1 = 0ull, a2 = 0ull, a3 = 0ull;
#pragma unroll
                for (int q = 0; q < 8; ++q) {
                    ulonglong2 hv = hb4[q];
                    fma2(a0, w2[0 * 16 + 2 * q], hv.x); fma2(a0, w2[0 * 16 + 2 * q + 1], hv.y);
                    fma2(a1, w2[1 * 16 + 2 * q], hv.x); fma2(a1, w2[1 * 16 + 2 * q + 1], hv.y);
                    fma2(a2, w2[2 * 16 + 2 * q], hv.x); fma2(a2, w2[2 * 16 + 2 * q + 1], hv.y);
                    fma2(a3, w2[3 * 16 + 2 * q], hv.x); fma2(a3, w2[3 * 16 + 2 * q + 1], hv.y);
                }
                float4 part;
                part.x = lo2(a0) + hi2(a0);
                part.y = lo2(a1) + hi2(a1);
                part.z = lo2(a2) + hi2(a2);
                part.w = lo2(a3) + hi2(a3);
                *(float4*)&gs[((1 * 8 + kc) * 4 + b) * 128 + 4 * rg] = part;
            }
        }

        __syncthreads();   // sync2: gsB complete; orders gsA reads vs t+1 kA

        // ---- actB (warps 4-7) + send B's h
        if (half == 1) {
            float pi = gi0, pf = gi1, pg = gi2, po = gi3;
            if (t > 0) {
#pragma unroll
                for (int q = 0; q < 8; ++q) {
                    const float* gq = gs + ((1 * 8 + q) * 4 + bb) * 128 + aj;
                    pi += gq[0];
                    pf += gq[32];
                    pg += gq[64];
                    po += gq[96];
                }
            }
            float iv = sigf(pi), fv = sigf(pf), gv = tanh_fast(pg), ov = sigf(po);
            c_reg = fv * c_reg + iv * gv;
            float h = ov * tanh_fast(c_reg);
            ghout[(size_t)t * NH] = h;

            float hn = __shfl_down_sync(0xffffffffu, h, 1);
            if ((aj & 1) == 0) {
                unsigned long long hp =
                    ((unsigned long long)__float_as_uint(hn) << 32) |
                    (unsigned long long)__float_as_uint(h);
                const uint32_t dsto = (uint32_t)(nxt * 2048 * 4) + h_slot;
                const uint32_t mbo  = (uint32_t)(128 + nxt * 64 + (int)rank * 8); // B[nxt][me]
#pragma unroll
                for (int r = 0; r < 8; ++r) {
                    asm volatile(
                        "st.async.shared::cluster.mbarrier::complete_tx::bytes.b64 [%0], %1, [%2];"
                        :: "r"(rhs[r] + dsto), "l"(hp), "r"(rmb[r] + mbo) : "memory");
                }
            }
        }

        gi0 = ni0; gi1 = ni1; gi2 = ni2; gi3 = ni3;
    }

    // drain final sends (t=255: nxt=0 -> A[0][kc], B[0][kc]); per-warp waits
    MBWAIT_CTA(mb_sh + (uint32_t)(kc * 8), pA0);
    MBWAIT_CTA(mb_sh + (uint32_t)(128 + kc * 8), pB0);
    asm volatile("barrier.cluster.arrive.aligned;" ::: "memory");
    asm volatile("barrier.cluster.wait.aligned;" ::: "memory");
}

// ---------------------------------------------------------------------------
// Kernel 3: emissions. One warp per (b,t); lane = tag. 4 acc chains.
// ---------------------------------------------------------------------------
__global__ void __launch_bounds__(256) emissions_kernel(
    const int* __restrict__ lens, const float* __restrict__ b_out)
{
    const int item = blockIdx.x * 8 + (threadIdx.x >> 5);
    const int lane = threadIdx.x & 31;
    const int b = item >> 8, t = item & 255;
    const int len = lens[b];
    const int tb = (t < len) ? (len - 1 - t) : t;

    const float* hf = g_h + ((size_t)0 * NB + b) * NT * NH + (size_t)t * NH;
    const float* hb = g_h + ((size_t)1 * NB + b) * NT * NH + (size_t)tb * NH;
    const float* __restrict__ wT = g_wOutT;

    float acc0 = b_out[lane], acc1 = 0.f, acc2 = 0.f, acc3 = 0.f;
#pragma unroll 4
    for (int k16 = 0; k16 < 16; ++k16) {
        float4 ha = *(const float4*)(hf + k16 * 16);
        float4 hbv = *(const float4*)(hf + k16 * 16 + 4);
        float4 hc = *(const float4*)(hf + k16 * 16 + 8);
        float4 hd = *(const float4*)(hf + k16 * 16 + 12);
        const float* w0 = wT + (k16 * 16) * NC + lane;
        acc0 = fmaf(ha.x, w0[0 * NC], acc0);  acc1 = fmaf(ha.y, w0[1 * NC], acc1);
        acc2 = fmaf(ha.z, w0[2 * NC], acc2);  acc3 = fmaf(ha.w, w0[3 * NC], acc3);
        acc0 = fmaf(hbv.x, w0[4 * NC], acc0); acc1 = fmaf(hbv.y, w0[5 * NC], acc1);
        acc2 = fmaf(hbv.z, w0[6 * NC], acc2); acc3 = fmaf(hbv.w, w0[7 * NC], acc3);
        acc0 = fmaf(hc.x, w0[8 * NC], acc0);  acc1 = fmaf(hc.y, w0[9 * NC], acc1);
        acc2 = fmaf(hc.z, w0[10 * NC], acc2); acc3 = fmaf(hc.w, w0[11 * NC], acc3);
        acc0 = fmaf(hd.x, w0[12 * NC], acc0); acc1 = fmaf(hd.y, w0[13 * NC], acc1);
        acc2 = fmaf(hd.z, w0[14 * NC], acc2); acc3 = fmaf(hd.w, w0[15 * NC], acc3);
    }
#pragma unroll 4
    for (int k16 = 0; k16 < 16; ++k16) {
        float4 ha = *(const float4*)(hb + k16 * 16);
        float4 hbv = *(const float4*)(hb + k16 * 16 + 4);
        float4 hc = *(const float4*)(hb + k16 * 16 + 8);
        float4 hd = *(const float4*)(hb + k16 * 16 + 12);
        const float* w0 = wT + (NH + k16 * 16) * NC + lane;
        acc0 = fmaf(ha.x, w0[0 * NC], acc0);  acc1 = fmaf(ha.y, w0[1 * NC], acc1);
        acc2 = fmaf(ha.z, w0[2 * NC], acc2);  acc3 = fmaf(ha.w, w0[3 * NC], acc3);
        acc0 = fmaf(hbv.x, w0[4 * NC], acc0); acc1 = fmaf(hbv.y, w0[5 * NC], acc1);
        acc2 = fmaf(hbv.z, w0[6 * NC], acc2); acc3 = fmaf(hbv.w, w0[7 * NC], acc3);
        acc0 = fmaf(hc.x, w0[8 * NC], acc0);  acc1 = fmaf(hc.y, w0[9 * NC], acc1);
        acc2 = fmaf(hc.z, w0[10 * NC], acc2); acc3 = fmaf(hc.w, w0[11 * NC], acc3);
        acc0 = fmaf(hd.x, w0[12 * NC], acc0); acc1 = fmaf(hd.y, w0[13 * NC], acc1);
        acc2 = fmaf(hd.z, w0[14 * NC], acc2); acc3 = fmaf(hd.w, w0[15 * NC], acc3);
    }
    g_em[(size_t)item * NC + lane] = (acc0 + acc1) + (acc2 + acc3);
}

// ---------------------------------------------------------------------------
// Kernel 4: Viterbi decode. One warp per batch element; lane = tag.
// ---------------------------------------------------------------------------
__global__ void __launch_bounds__(32) viterbi_kernel(
    const int* __restrict__ lens,
    const float* __restrict__ start_trans, const float* __restrict__ end_trans,
    const float* __restrict__ trans, float* __restrict__ out)
{
    const int b = blockIdx.x;
    const int lane = threadIdx.x;

    __shared__ int hist[NT - 1][NC];

    float tr[NC];
#pragma unroll
    for (int cp = 0; cp < NC; ++cp) tr[cp] = trans[cp * NC + lane];

    const int len = lens[b];
    const float* emp = g_em + (size_t)b * NT * NC;
    float score = start_trans[lane] + emp[lane];
    float em_next = emp[NC + lane];

    for (int t = 1; t < NT; ++t) {
        float best = -1e30f;
        int bp = 0;
#pragma unroll
        for (int cp = 0; cp < NC; ++cp) {
            float sc = __shfl_sync(0xffffffffu, score, cp) + tr[cp];
            if (sc > best) { best = sc; bp = cp; }
        }
        hist[t - 1][lane] = bp;
        float em_cur = em_next;
        if (t + 1 < NT) em_next = emp[(t + 1) * NC + lane];
        if (t < len) score = best + em_cur;
    }
    score += end_trans[lane];

    float v = score;
    int idx = lane;
#pragma unroll
    for (int off = 16; off; off >>= 1) {
        float v2 = __shfl_xor_sync(0xffffffffu, v, off);
        int i2 = __shfl_xor_sync(0xffffffffu, idx, off);
        if (v2 > v || (v2 == v && i2 < idx)) { v = v2; idx = i2; }
    }

    if (lane == 0) {
        out[NB * NT + b] = v;
        int tag = idx;
        out[(size_t)b * NT + (NT - 1)] = (float)tag;
        for (int t = NT - 2; t >= 0; --t) {
            if (t < len - 1) tag = hist[t][tag];
            out[(size_t)b * NT + t] = (float)tag;
        }
    }
}

// ---------------------------------------------------------------------------
extern "C" void kernel_launch(void* const* d_in, const int* in_sizes, int n_in,
                              void* d_out, int out_size)
{
    const int*   sent   = (const int*)d_in[0];
    const int*   lens   = (const int*)d_in[1];
    const float* emb    = (const float*)d_in[2];
    const float* w_ih_f = (const float*)d_in[3];
    const float* w_hh_f = (const float*)d_in[4];
    const float* b_ih_f = (const float*)d_in[5];
    const float* b_hh_f = (const float*)d_in[6];
    const float* w_ih_b = (const float*)d_in[7];
    const float* w_hh_b = (const float*)d_in[8];
    const float* b_ih_b = (const float*)d_in[9];
    const float* b_hh_b = (const float*)d_in[10];
    const float* w_out  = (const float*)d_in[11];
    const float* b_out  = (const float*)d_in[12];
    const float* start_trans = (const float*)d_in[13];
    const float* end_trans   = (const float*)d_in[14];
    const float* trans       = (const float*)d_in[15];
    float* out = (float*)d_out;

    cudaFuncSetAttribute(lstm_cluster_kernel,
                         cudaFuncAttributeMaxDynamicSharedMemorySize, LSMEM_BYTES);

    // 1 dummy: shifts ncu's fixed capture index onto lstm_cluster_kernel.
    dummy_kernel<<<1, 32>>>();

    dim3 tb(32, 8);
    transpose_wout_kernel<<<dim3((2 * NH) / 32, 1, 1), tb>>>(w_out);

    dim3 g1(128, 16);
    input_proj_kernel<<<g1, 256>>>(sent, lens, emb,
                                   w_ih_f, b_ih_f, b_hh_f,
                                   w_ih_b, b_ih_b, b_hh_b);
    lstm_cluster_kernel<<<128, 256, LSMEM_BYTES>>>(w_hh_f, w_hh_b);
    emissions_kernel<<<NB * NT / 8, 256>>>(lens, b_out);
    viterbi_kernel<<<NB, 32>>>(lens, start_trans, end_trans, trans, out);
}